// round 3
// baseline (speedup 1.0000x reference)
#include <cuda_runtime.h>
#include <cuda_bf16.h>

// Problem constants (GCN_71124658421835)
#define NMAX  50000
#define EMAX  1600000
#define FIN   256
#define HID   64
#define FOUT  128

// Scratch (no allocation allowed -> __device__ globals)
__device__ __align__(16) float g_dinv[NMAX];
__device__ __align__(16) float g_hs1 [NMAX * HID];     // (x@W1)*dinv
__device__ __align__(16) float g_h   [NMAX * HID];     // layer-1 output (relu'd)
__device__ __align__(16) float g_hs2 [NMAX * FOUT];    // (h@W2)*dinv
__device__ int g_hist[NMAX];
__device__ int g_off [NMAX + 1];
__device__ int g_cur [NMAX];
__device__ int g_srt [EMAX];                           // src sorted by dst (CSR adj)

// ---------------------------------------------------------------------------
// CSR construction: histogram -> scan -> place
// ---------------------------------------------------------------------------
__global__ void k_zero_hist(int* hist, int n) {
    int i = blockIdx.x * blockDim.x + threadIdx.x;
    if (i < n) hist[i] = 0;
}

__global__ void k_hist(const int* __restrict__ dst, int* hist, int E) {
    int i = blockIdx.x * blockDim.x + threadIdx.x;
    if (i < E) atomicAdd(&hist[dst[i]], 1);
}

// Single-block exclusive scan over hist, also emits dinv.
__global__ void k_scan(const int* __restrict__ hist, int* __restrict__ off,
                       int* __restrict__ cur, float* __restrict__ dinv, int n)
{
    __shared__ int sums[1024];
    const int t = threadIdx.x;                  // blockDim.x == 1024
    const int chunk = (n + 1023) >> 10;
    const int lo = t * chunk;
    const int hi = min(lo + chunk, n);

    int s = 0;
    for (int i = lo; i < hi; i++) s += hist[i];
    sums[t] = s;
    __syncthreads();
    // Hillis-Steele inclusive scan
    for (int d = 1; d < 1024; d <<= 1) {
        int v = (t >= d) ? sums[t - d] : 0;
        __syncthreads();
        sums[t] += v;
        __syncthreads();
    }
    int run = (t == 0) ? 0 : sums[t - 1];
    for (int i = lo; i < hi; i++) {
        int c = hist[i];
        off[i]  = run;
        cur[i]  = run;
        dinv[i] = rsqrtf((float)c + 1.0f);      // +1 self loop
        run += c;
    }
    if (t == 1023) off[n] = sums[1023];
}

__global__ void k_place(const int* __restrict__ src,
                        const int* __restrict__ dst,
                        int* cur, int* __restrict__ srt, int E)
{
    int i = blockIdx.x * blockDim.x + threadIdx.x;
    if (i < E) {
        int d = dst[i];
        int p = atomicAdd(&cur[d], 1);
        srt[p] = src[i];
    }
}

// ---------------------------------------------------------------------------
// Tiled SGEMM: C[row] = (A@B)[row] * dinv[row]
// A[M,K] row-major, B[K,N] row-major. TN must be 4.
// ---------------------------------------------------------------------------
template<int BM, int BN, int BK, int TM, int TN>
__global__ void k_gemm_scaled(const float* __restrict__ A, const float* __restrict__ B,
                              const float* __restrict__ dinv,
                              float* __restrict__ C, int M, int N, int K)
{
    constexpr int THREADS = (BM / TM) * (BN / TN);
    __shared__ float As[BK][BM];
    __shared__ float Bs[BK][BN];

    const int tid = threadIdx.x;
    const int bm  = blockIdx.x * BM;
    const int bn  = blockIdx.y * BN;
    const int tx  = tid % (BN / TN);
    const int ty  = tid / (BN / TN);

    float acc[TM][TN];
#pragma unroll
    for (int i = 0; i < TM; i++)
#pragma unroll
        for (int j = 0; j < TN; j++) acc[i][j] = 0.0f;

    constexpr int A_V4  = BM * BK / 4;
    constexpr int A_PER = A_V4 / THREADS;
    constexpr int B_V4  = BK * BN / 4;
    constexpr int B_PER = B_V4 / THREADS;
    static_assert(A_PER * THREADS == A_V4, "A tile");
    static_assert(B_PER * THREADS == B_V4, "B tile");

    for (int k0 = 0; k0 < K; k0 += BK) {
#pragma unroll
        for (int i = 0; i < A_PER; i++) {
            int v  = tid + i * THREADS;
            int r  = v / (BK / 4);
            int c4 = (v % (BK / 4)) * 4;
            int row = bm + r;
            float4 a = make_float4(0.f, 0.f, 0.f, 0.f);
            if (row < M)
                a = *(const float4*)&A[(long long)row * K + k0 + c4];
            As[c4 + 0][r] = a.x;
            As[c4 + 1][r] = a.y;
            As[c4 + 2][r] = a.z;
            As[c4 + 3][r] = a.w;
        }
#pragma unroll
        for (int i = 0; i < B_PER; i++) {
            int v  = tid + i * THREADS;
            int r  = v / (BN / 4);
            int c4 = (v % (BN / 4)) * 4;
            *(float4*)&Bs[r][c4] = *(const float4*)&B[(long long)(k0 + r) * N + bn + c4];
        }
        __syncthreads();

#pragma unroll
        for (int k = 0; k < BK; k++) {
            float ra[TM], rb[TN];
#pragma unroll
            for (int i = 0; i < TM; i++) ra[i] = As[k][ty * TM + i];
#pragma unroll
            for (int j = 0; j < TN; j++) rb[j] = Bs[k][tx * TN + j];
#pragma unroll
            for (int i = 0; i < TM; i++)
#pragma unroll
                for (int j = 0; j < TN; j++) acc[i][j] += ra[i] * rb[j];
        }
        __syncthreads();
    }

#pragma unroll
    for (int i = 0; i < TM; i++) {
        int row = bm + ty * TM + i;
        if (row >= M) continue;
        float s = dinv[row];
        float4 v;
        v.x = acc[i][0] * s;
        v.y = acc[i][1] * s;
        v.z = acc[i][2] * s;
        v.w = acc[i][3] * s;
        *(float4*)&C[(long long)row * N + bn + tx * TN] = v;
    }
}

// ---------------------------------------------------------------------------
// CSR gather-aggregate, fused epilogue:
//   out[node,f] = act( dinv[node] * (hs[node,f] + sum_{s in adj(node)} hs[s,f]) + b[f] )
// One block per node, F threads per block (F = 64 or 128).
// ---------------------------------------------------------------------------
template<int F, bool RELU>
__global__ void k_gather(const float* __restrict__ hs,
                         const int*   __restrict__ off,
                         const int*   __restrict__ srt,
                         const float* __restrict__ dinv,
                         const float* __restrict__ bias,
                         float* __restrict__ out)
{
    const int node = blockIdx.x;
    const int f    = threadIdx.x;

    float acc = hs[node * F + f];               // self-loop term (pre-scaled by dinv)
    const int beg = off[node];
    const int end = off[node + 1];

    int j = beg;
    for (; j + 2 <= end; j += 2) {
        int s0 = __ldg(&srt[j]);
        int s1 = __ldg(&srt[j + 1]);
        float v0 = __ldg(&hs[s0 * F + f]);
        float v1 = __ldg(&hs[s1 * F + f]);
        acc += v0;
        acc += v1;
    }
    if (j < end) {
        int s = __ldg(&srt[j]);
        acc += __ldg(&hs[s * F + f]);
    }

    float v = fmaf(dinv[node], acc, bias[f]);
    if (RELU) v = fmaxf(v, 0.0f);
    out[node * F + f] = v;
}

// ---------------------------------------------------------------------------
extern "C" void kernel_launch(void* const* d_in, const int* in_sizes, int n_in,
                              void* d_out, int out_size)
{
    const float* x   = (const float*)d_in[0];
    const int*   ei  = (const int*)d_in[1];      // int64 in reference -> int32 in harness
    const float* W1  = (const float*)d_in[2];
    const float* b1  = (const float*)d_in[3];
    const float* W2  = (const float*)d_in[4];
    const float* b2  = (const float*)d_in[5];
    float*       out = (float*)d_out;

    const int N = in_sizes[0] / FIN;     // 50000
    const int E = in_sizes[1] / 2;       // 1.6M
    const int* src = ei;
    const int* dst = ei + E;

    float *dinv, *hs1, *h, *hs2;
    int *hist, *off, *cur, *srt;
    cudaGetSymbolAddress((void**)&dinv, g_dinv);
    cudaGetSymbolAddress((void**)&hs1,  g_hs1);
    cudaGetSymbolAddress((void**)&h,    g_h);
    cudaGetSymbolAddress((void**)&hs2,  g_hs2);
    cudaGetSymbolAddress((void**)&hist, g_hist);
    cudaGetSymbolAddress((void**)&off,  g_off);
    cudaGetSymbolAddress((void**)&cur,  g_cur);
    cudaGetSymbolAddress((void**)&srt,  g_srt);

    const int T = 256;

    // --- CSR by dst + dinv ---
    k_zero_hist<<<(N + T - 1) / T, T>>>(hist, N);
    k_hist     <<<(E + T - 1) / T, T>>>(dst, hist, E);
    k_scan     <<<1, 1024>>>(hist, off, cur, dinv, N);
    k_place    <<<(E + T - 1) / T, T>>>(src, dst, cur, srt, E);

    // --- layer 1 ---
    {
        dim3 grid((N + 127) / 128, HID / 64);
        k_gemm_scaled<128, 64, 16, 8, 4><<<grid, 256>>>(x, W1, dinv, hs1, N, HID, FIN);
    }
    k_gather<HID, true><<<N, HID>>>(hs1, off, srt, dinv, b1, h);

    // --- layer 2 ---
    {
        dim3 grid((N + 127) / 128, FOUT / 64);
        k_gemm_scaled<128, 64, 16, 8, 4><<<grid, 256>>>(h, W2, dinv, hs2, N, FOUT, HID);
    }
    k_gather<FOUT, false><<<N, FOUT>>>(hs2, off, srt, dinv, b2, out);
}

// round 5
// speedup vs baseline: 1.1983x; 1.1983x over previous
#include <cuda_runtime.h>
#include <cuda_bf16.h>
#include <cstdint>

// Problem constants (GCN_71124658421835)
#define NMAX  50000
#define EMAX  1600000
#define FIN   256
#define HID   64
#define FOUT  128

// Scratch (no allocation allowed -> __device__ globals)
__device__ __align__(16) float g_dinv[NMAX];
__device__ __align__(16) float g_hs1 [NMAX * HID];     // (x@W1)*dinv
__device__ __align__(16) float g_hh1 [NMAX * HID];     // relu(gcn1)*dinv
__device__ __align__(16) float g_hh2 [NMAX * HID];     // A_hat @ h
__device__ int g_hist[NMAX];
__device__ int g_off [NMAX + 1];
__device__ int g_cur [NMAX];
__device__ int g_srt [EMAX];                           // src sorted by dst (CSR adj)

// ---------------------------------------------------------------------------
// CSR construction: histogram -> scan -> place
// ---------------------------------------------------------------------------
__global__ void k_hist4(const int4* __restrict__ dst4, int* hist, int E4) {
    int i = blockIdx.x * blockDim.x + threadIdx.x;
    if (i < E4) {
        int4 d = __ldg(&dst4[i]);
        atomicAdd(&hist[d.x], 1);
        atomicAdd(&hist[d.y], 1);
        atomicAdd(&hist[d.z], 1);
        atomicAdd(&hist[d.w], 1);
    }
}

__global__ void k_hist1(const int* __restrict__ dst, int* hist, int E, int base) {
    int i = base + blockIdx.x * blockDim.x + threadIdx.x;
    if (i < E) atomicAdd(&hist[dst[i]], 1);
}

// Single-block exclusive scan over hist, also emits dinv.
__global__ void k_scan(const int* __restrict__ hist, int* __restrict__ off,
                       int* __restrict__ cur, float* __restrict__ dinv, int n)
{
    __shared__ int sums[1024];
    const int t = threadIdx.x;                  // blockDim.x == 1024
    const int chunk = (n + 1023) >> 10;
    const int lo = t * chunk;
    const int hi = min(lo + chunk, n);

    int s = 0;
    for (int i = lo; i < hi; i++) s += hist[i];
    sums[t] = s;
    __syncthreads();
    for (int d = 1; d < 1024; d <<= 1) {
        int v = (t >= d) ? sums[t - d] : 0;
        __syncthreads();
        sums[t] += v;
        __syncthreads();
    }
    int run = (t == 0) ? 0 : sums[t - 1];
    for (int i = lo; i < hi; i++) {
        int c = hist[i];
        off[i]  = run;
        cur[i]  = run;
        dinv[i] = rsqrtf((float)c + 1.0f);      // +1 self loop
        run += c;
    }
    if (t == 1023) off[n] = sums[1023];
}

__global__ void k_place(const int* __restrict__ src,
                        const int* __restrict__ dst,
                        int* cur, int* __restrict__ srt, int E)
{
    int i = blockIdx.x * blockDim.x + threadIdx.x;
    if (i < E) {
        int d = dst[i];
        int p = atomicAdd(&cur[d], 1);
        srt[p] = src[i];
    }
}

// ---------------------------------------------------------------------------
// Tiled SGEMM: C[row,col] = (A@B)[row,col] , epilogue:
//   DOSCALE: * dinv[row]      DOBIAS: + bias[col]
// A[M,K] row-major, B[K,N] row-major. TN must be 4.
// ---------------------------------------------------------------------------
template<int BM, int BN, int BK, int TM, int TN, bool DOSCALE, bool DOBIAS>
__global__ void k_gemm(const float* __restrict__ A, const float* __restrict__ B,
                       const float* __restrict__ dinv, const float* __restrict__ bias,
                       float* __restrict__ C, int M, int N, int K)
{
    constexpr int THREADS = (BM / TM) * (BN / TN);
    __shared__ float As[BK][BM];
    __shared__ float Bs[BK][BN];

    const int tid = threadIdx.x;
    const int bm  = blockIdx.x * BM;
    const int bn  = blockIdx.y * BN;
    const int tx  = tid % (BN / TN);
    const int ty  = tid / (BN / TN);

    float acc[TM][TN];
#pragma unroll
    for (int i = 0; i < TM; i++)
#pragma unroll
        for (int j = 0; j < TN; j++) acc[i][j] = 0.0f;

    constexpr int A_V4  = BM * BK / 4;
    constexpr int A_PER = A_V4 / THREADS;
    constexpr int B_V4  = BK * BN / 4;
    constexpr int B_PER = B_V4 / THREADS;
    static_assert(A_PER * THREADS == A_V4, "A tile");
    static_assert(B_PER * THREADS == B_V4, "B tile");

    for (int k0 = 0; k0 < K; k0 += BK) {
#pragma unroll
        for (int i = 0; i < A_PER; i++) {
            int v  = tid + i * THREADS;
            int r  = v / (BK / 4);
            int c4 = (v % (BK / 4)) * 4;
            int row = bm + r;
            float4 a = make_float4(0.f, 0.f, 0.f, 0.f);
            if (row < M)
                a = *(const float4*)&A[(long long)row * K + k0 + c4];
            As[c4 + 0][r] = a.x;
            As[c4 + 1][r] = a.y;
            As[c4 + 2][r] = a.z;
            As[c4 + 3][r] = a.w;
        }
#pragma unroll
        for (int i = 0; i < B_PER; i++) {
            int v  = tid + i * THREADS;
            int r  = v / (BN / 4);
            int c4 = (v % (BN / 4)) * 4;
            *(float4*)&Bs[r][c4] = *(const float4*)&B[(long long)(k0 + r) * N + bn + c4];
        }
        __syncthreads();

#pragma unroll
        for (int k = 0; k < BK; k++) {
            float ra[TM], rb[TN];
#pragma unroll
            for (int i = 0; i < TM; i++) ra[i] = As[k][ty * TM + i];
#pragma unroll
            for (int j = 0; j < TN; j++) rb[j] = Bs[k][tx * TN + j];
#pragma unroll
            for (int i = 0; i < TM; i++)
#pragma unroll
                for (int j = 0; j < TN; j++) acc[i][j] += ra[i] * rb[j];
        }
        __syncthreads();
    }

    float4 bb = make_float4(0.f, 0.f, 0.f, 0.f);
    if (DOBIAS) bb = *(const float4*)&bias[bn + tx * TN];

#pragma unroll
    for (int i = 0; i < TM; i++) {
        int row = bm + ty * TM + i;
        if (row >= M) continue;
        float s = DOSCALE ? dinv[row] : 1.0f;
        float4 v;
        v.x = acc[i][0];
        v.y = acc[i][1];
        v.z = acc[i][2];
        v.w = acc[i][3];
        if (DOSCALE) { v.x *= s; v.y *= s; v.z *= s; v.w *= s; }
        if (DOBIAS)  { v.x += bb.x; v.y += bb.y; v.z += bb.z; v.w += bb.w; }
        *(float4*)&C[(long long)row * N + bn + tx * TN] = v;
    }
}

// ---------------------------------------------------------------------------
// CSR gather-aggregate over 64 features (16 float4 lanes per node).
// acc = hs[node] + sum_{s in adj(node)} hs[s]        (hs prescaled by dinv[src])
// r = dinv[node]*acc ; optionally + bias, relu, * dinv[node] (prescale for next)
// Block = 256 threads = 16 nodes.
// ---------------------------------------------------------------------------
template<bool BIAS, bool RELU, bool PRESCALE>
__global__ void k_gather64(const float4* __restrict__ hs,
                           const int*   __restrict__ off,
                           const int*   __restrict__ srt,
                           const float* __restrict__ dinv,
                           const float* __restrict__ bias,
                           float4* __restrict__ out, int N)
{
    const int tid  = threadIdx.x;
    const int node = blockIdx.x * 16 + (tid >> 4);
    const int nl   = tid & 15;
    if (node >= N) return;

    float4 acc = __ldg(&hs[node * 16 + nl]);    // self-loop term
    int       j   = __ldg(&off[node]);
    const int end = __ldg(&off[node + 1]);

    for (; j + 2 <= end; j += 2) {
        int s0 = __ldg(&srt[j]);
        int s1 = __ldg(&srt[j + 1]);
        float4 a = __ldg(&hs[s0 * 16 + nl]);
        float4 b = __ldg(&hs[s1 * 16 + nl]);
        acc.x += a.x + b.x;
        acc.y += a.y + b.y;
        acc.z += a.z + b.z;
        acc.w += a.w + b.w;
    }
    if (j < end) {
        int s = __ldg(&srt[j]);
        float4 a = __ldg(&hs[s * 16 + nl]);
        acc.x += a.x; acc.y += a.y; acc.z += a.z; acc.w += a.w;
    }

    const float s = __ldg(&dinv[node]);
    float4 r;
    r.x = acc.x * s; r.y = acc.y * s; r.z = acc.z * s; r.w = acc.w * s;
    if (BIAS) {
        float4 b = *(const float4*)&bias[nl * 4];
        r.x += b.x; r.y += b.y; r.z += b.z; r.w += b.w;
    }
    if (RELU) {
        r.x = fmaxf(r.x, 0.f); r.y = fmaxf(r.y, 0.f);
        r.z = fmaxf(r.z, 0.f); r.w = fmaxf(r.w, 0.f);
    }
    if (PRESCALE) { r.x *= s; r.y *= s; r.z *= s; r.w *= s; }
    out[node * 16 + nl] = r;
}

// ---------------------------------------------------------------------------
extern "C" void kernel_launch(void* const* d_in, const int* in_sizes, int n_in,
                              void* d_out, int out_size)
{
    const float* x   = (const float*)d_in[0];
    const int*   ei  = (const int*)d_in[1];      // int64 in reference -> int32 in harness
    const float* W1  = (const float*)d_in[2];
    const float* b1  = (const float*)d_in[3];
    const float* W2  = (const float*)d_in[4];
    const float* b2  = (const float*)d_in[5];
    float*       out = (float*)d_out;

    const int N = in_sizes[0] / FIN;     // 50000
    const int E = in_sizes[1] / 2;       // 1.6M
    const int* src = ei;
    const int* dst = ei + E;

    float *dinv, *hs1, *hh1, *hh2;
    int *hist, *off, *cur, *srt;
    cudaGetSymbolAddress((void**)&dinv, g_dinv);
    cudaGetSymbolAddress((void**)&hs1,  g_hs1);
    cudaGetSymbolAddress((void**)&hh1,  g_hh1);
    cudaGetSymbolAddress((void**)&hh2,  g_hh2);
    cudaGetSymbolAddress((void**)&hist, g_hist);
    cudaGetSymbolAddress((void**)&off,  g_off);
    cudaGetSymbolAddress((void**)&cur,  g_cur);
    cudaGetSymbolAddress((void**)&srt,  g_srt);

    const int T = 256;

    // --- CSR by dst + dinv ---
    cudaMemsetAsync(hist, 0, N * sizeof(int));
    const bool can_v4 = (E % 4 == 0) && ((((unsigned long long)dst) & 15ull) == 0);
    if (can_v4) {
        int E4 = E / 4;
        k_hist4<<<(E4 + T - 1) / T, T>>>((const int4*)dst, hist, E4);
    } else {
        k_hist1<<<(E + T - 1) / T, T>>>(dst, hist, E, 0);
    }
    k_scan <<<1, 1024>>>(hist, off, cur, dinv, N);
    k_place<<<(E + T - 1) / T, T>>>(src, dst, cur, srt, E);

    // --- layer 1: hs1 = (x@W1)*dinv ---
    {
        dim3 grid((N + 127) / 128, HID / 64);
        k_gemm<128, 64, 16, 8, 4, true, false><<<grid, 256>>>(x, W1, dinv, nullptr,
                                                              hs1, N, HID, FIN);
    }
    // hh1 = relu(dinv*(hs1_i + sum hs1_s) + b1) * dinv
    k_gather64<true, true, true><<<(N + 15) / 16, 256>>>((const float4*)hs1, off, srt,
                                                         dinv, b1, (float4*)hh1, N);
    // --- layer 2 aggregation first: hh2 = dinv*(hh1_i + sum hh1_s) = A_hat @ h ---
    k_gather64<false, false, false><<<(N + 15) / 16, 256>>>((const float4*)hh1, off, srt,
                                                            dinv, nullptr, (float4*)hh2, N);
    // out = hh2 @ W2 + b2
    {
        dim3 grid((N + 127) / 128, FOUT / 64);
        k_gemm<128, 64, 16, 8, 4, false, true><<<grid, 256>>>(hh2, W2, nullptr, b2,
                                                              out, N, FOUT, HID);
    }
}